// round 1
// baseline (speedup 1.0000x reference)
#include <cuda_runtime.h>
#include <cuda_bf16.h>
#include <cstddef>

#define Bsz   4
#define Tsz   2048
#define Csz   1024
#define Hn    16
#define Dh    64
#define Mrows (Bsz * Tsz)   // 8192

// Scratch (static __device__ arrays — allocation-guard safe)
__device__ float g_qkv[(size_t)Mrows * 3 * Csz];   // [8192, 3072]
__device__ float g_y  [(size_t)Mrows * Csz];       // [8192, 1024]

// ---------------------------------------------------------------------------
// Tiled fp32 GEMM: C[M,N] = A[M,K] @ B[K,N] + bias[N]
// 128x128x16 tile, 256 threads, 8x8 register blocking.
// ---------------------------------------------------------------------------
__device__ __forceinline__ void gemm_body(
    const float* __restrict__ A, const float* __restrict__ B,
    const float* __restrict__ bias, float* __restrict__ C,
    int M, int N, int K,
    float* As /*[16*132] transposed: As[k*132+m]*/,
    float* Bs /*[16*128]: Bs[k*128+n]*/)
{
    const int BK = 16;
    int tid = threadIdx.x;
    int tx  = tid & 15;
    int ty  = tid >> 4;
    int row0 = blockIdx.y * 128;
    int col0 = blockIdx.x * 128;

    float acc[8][8];
    #pragma unroll
    for (int i = 0; i < 8; i++)
        #pragma unroll
        for (int j = 0; j < 8; j++) acc[i][j] = 0.f;

    for (int kt = 0; kt < K; kt += BK) {
        // load A tile (128x16) transposed + B tile (16x128)
        #pragma unroll
        for (int u = 0; u < 2; u++) {
            int idx = tid + u * 256;              // 0..511
            int r   = idx >> 2;                    // 0..127
            int c4  = (idx & 3) * 4;               // 0,4,8,12
            float4 a4 = *(const float4*)&A[(size_t)(row0 + r) * K + kt + c4];
            As[(c4 + 0) * 132 + r] = a4.x;
            As[(c4 + 1) * 132 + r] = a4.y;
            As[(c4 + 2) * 132 + r] = a4.z;
            As[(c4 + 3) * 132 + r] = a4.w;
            int br  = idx >> 5;                    // 0..15
            int bc4 = (idx & 31) * 4;              // 0..124
            *(float4*)&Bs[br * 128 + bc4] =
                *(const float4*)&B[(size_t)(kt + br) * N + col0 + bc4];
        }
        __syncthreads();

        #pragma unroll
        for (int k = 0; k < BK; k++) {
            float4 a0 = *(float4*)&As[k * 132 + ty * 8];
            float4 a1 = *(float4*)&As[k * 132 + ty * 8 + 4];
            float4 b0 = *(float4*)&Bs[k * 128 + tx * 8];
            float4 b1 = *(float4*)&Bs[k * 128 + tx * 8 + 4];
            float ar[8] = {a0.x, a0.y, a0.z, a0.w, a1.x, a1.y, a1.z, a1.w};
            float br_[8] = {b0.x, b0.y, b0.z, b0.w, b1.x, b1.y, b1.z, b1.w};
            #pragma unroll
            for (int i = 0; i < 8; i++)
                #pragma unroll
                for (int j = 0; j < 8; j++)
                    acc[i][j] += ar[i] * br_[j];
        }
        __syncthreads();
    }

    #pragma unroll
    for (int i = 0; i < 8; i++) {
        int r = row0 + ty * 8 + i;
        #pragma unroll
        for (int j4 = 0; j4 < 8; j4 += 4) {
            int c = col0 + tx * 8 + j4;
            float4 o;
            o.x = acc[i][j4 + 0] + bias[c + 0];
            o.y = acc[i][j4 + 1] + bias[c + 1];
            o.z = acc[i][j4 + 2] + bias[c + 2];
            o.w = acc[i][j4 + 3] + bias[c + 3];
            *(float4*)&C[(size_t)r * N + c] = o;
        }
    }
}

__global__ __launch_bounds__(256) void gemm_qkv_kernel(
    const float* __restrict__ x, const float* __restrict__ W,
    const float* __restrict__ bias)
{
    __shared__ float As[16 * 132];
    __shared__ float Bs[16 * 128];
    gemm_body(x, W, bias, g_qkv, Mrows, 3 * Csz, Csz, As, Bs);
}

__global__ __launch_bounds__(256) void gemm_proj_kernel(
    const float* __restrict__ W, const float* __restrict__ bias,
    float* __restrict__ out)
{
    __shared__ float As[16 * 132];
    __shared__ float Bs[16 * 128];
    gemm_body(g_y, W, bias, out, Mrows, Csz, Csz, As, Bs);
}

// ---------------------------------------------------------------------------
// Flash attention, fp32. One CTA = one 64-query block of one (b,h).
// 256 threads as 16x16; each thread owns a 4x4 block of S and of O.
// Smem layouts (SP=68 stride, float4-aligned, conflict-mitigating pad):
//   Qt[d][r], Kt[d][c]  (transposed so S-compute reads both via LDS.128)
//   Vs[j][d], Pt[j][r]  (so O-update reads both via LDS.128)
// ---------------------------------------------------------------------------
#define SP 68

__global__ __launch_bounds__(256) void attn_kernel()
{
    extern __shared__ float sm[];
    float* Qt = sm;               // 64*SP
    float* Kt = Qt + 64 * SP;
    float* Vs = Kt + 64 * SP;
    float* Pt = Vs + 64 * SP;

    int qb = blockIdx.x;          // 0..31
    int bh = blockIdx.y;          // 0..63
    int b = bh >> 4, h = bh & 15;
    int tid = threadIdx.x;
    int tx = tid & 15, ty = tid >> 4;

    // load Q block transposed: Qt[d*SP + r]
    for (int i = tid; i < 64 * 64; i += 256) {
        int r = i >> 6, d = i & 63;
        Qt[d * SP + r] =
            g_qkv[(size_t)(b * Tsz + qb * 64 + r) * (3 * Csz) + h * Dh + d];
    }

    float m[4], l[4], acc[4][4];
    #pragma unroll
    for (int i = 0; i < 4; i++) {
        m[i] = -1e30f; l[i] = 0.f;
        #pragma unroll
        for (int j = 0; j < 4; j++) acc[i][j] = 0.f;
    }

    for (int kb = 0; kb <= qb; kb++) {
        __syncthreads();   // prev O-update done before overwriting K/V
        for (int i = tid; i < 64 * 64; i += 256) {
            int r = i >> 6, d = i & 63;
            size_t g = (size_t)(b * Tsz + kb * 64 + r) * (3 * Csz) + h * Dh + d;
            Kt[d * SP + r] = g_qkv[g + Csz];
            Vs[r * SP + d] = g_qkv[g + 2 * Csz];
        }
        __syncthreads();

        // S = Q K^T * 1/sqrt(D)
        float s[4][4];
        #pragma unroll
        for (int i = 0; i < 4; i++)
            #pragma unroll
            for (int j = 0; j < 4; j++) s[i][j] = 0.f;

        #pragma unroll 8
        for (int d = 0; d < 64; d++) {
            float4 q4 = *(float4*)&Qt[d * SP + ty * 4];
            float4 k4 = *(float4*)&Kt[d * SP + tx * 4];
            float qa[4] = {q4.x, q4.y, q4.z, q4.w};
            float ka[4] = {k4.x, k4.y, k4.z, k4.w};
            #pragma unroll
            for (int i = 0; i < 4; i++)
                #pragma unroll
                for (int j = 0; j < 4; j++)
                    s[i][j] += qa[i] * ka[j];
        }

        bool diag = (kb == qb);
        #pragma unroll
        for (int i = 0; i < 4; i++)
            #pragma unroll
            for (int j = 0; j < 4; j++) {
                s[i][j] *= 0.125f;   // 1/sqrt(64)
                if (diag && (tx * 4 + j) > (ty * 4 + i)) s[i][j] = -1e30f;
            }

        // online softmax per row (row r = ty*4+i, spread across 16 tx lanes)
        #pragma unroll
        for (int i = 0; i < 4; i++) {
            float mt = fmaxf(fmaxf(s[i][0], s[i][1]), fmaxf(s[i][2], s[i][3]));
            mt = fmaxf(mt, __shfl_xor_sync(0xffffffffu, mt, 1));
            mt = fmaxf(mt, __shfl_xor_sync(0xffffffffu, mt, 2));
            mt = fmaxf(mt, __shfl_xor_sync(0xffffffffu, mt, 4));
            mt = fmaxf(mt, __shfl_xor_sync(0xffffffffu, mt, 8));
            float mn = fmaxf(m[i], mt);
            float sc = __expf(m[i] - mn);
            float ps = 0.f;
            #pragma unroll
            for (int j = 0; j < 4; j++) {
                float p = __expf(s[i][j] - mn);
                s[i][j] = p;
                ps += p;
            }
            ps += __shfl_xor_sync(0xffffffffu, ps, 1);
            ps += __shfl_xor_sync(0xffffffffu, ps, 2);
            ps += __shfl_xor_sync(0xffffffffu, ps, 4);
            ps += __shfl_xor_sync(0xffffffffu, ps, 8);
            l[i] = l[i] * sc + ps;
            m[i] = mn;
            #pragma unroll
            for (int j = 0; j < 4; j++) {
                acc[i][j] *= sc;
                Pt[(tx * 4 + j) * SP + ty * 4 + i] = s[i][j];
            }
        }
        __syncthreads();   // Pt visible (and Vs still valid)

        // O += P V
        #pragma unroll 8
        for (int j = 0; j < 64; j++) {
            float4 p4 = *(float4*)&Pt[j * SP + ty * 4];
            float4 v4 = *(float4*)&Vs[j * SP + tx * 4];
            float pa[4] = {p4.x, p4.y, p4.z, p4.w};
            float va[4] = {v4.x, v4.y, v4.z, v4.w};
            #pragma unroll
            for (int i = 0; i < 4; i++)
                #pragma unroll
                for (int jd = 0; jd < 4; jd++)
                    acc[i][jd] += pa[i] * va[jd];
        }
    }

    // normalize & write y in [B,T,C] layout
    #pragma unroll
    for (int i = 0; i < 4; i++) {
        float inv = 1.f / l[i];
        float4 o;
        o.x = acc[i][0] * inv;
        o.y = acc[i][1] * inv;
        o.z = acc[i][2] * inv;
        o.w = acc[i][3] * inv;
        *(float4*)&g_y[(size_t)(b * Tsz + qb * 64 + ty * 4 + i) * Csz
                       + h * Dh + tx * 4] = o;
    }
}

// ---------------------------------------------------------------------------
extern "C" void kernel_launch(void* const* d_in, const int* in_sizes, int n_in,
                              void* d_out, int out_size)
{
    const float* x      = (const float*)d_in[0];
    const float* w_qkv  = (const float*)d_in[1];
    const float* b_qkv  = (const float*)d_in[2];
    const float* w_proj = (const float*)d_in[3];
    const float* b_proj = (const float*)d_in[4];
    float* out = (float*)d_out;

    // 1) qkv = x @ w_qkv + b_qkv   (M=8192, N=3072, K=1024)
    {
        dim3 grid(3 * Csz / 128, Mrows / 128);
        gemm_qkv_kernel<<<grid, 256>>>(x, w_qkv, b_qkv);
    }

    // 2) flash attention -> g_y
    {
        int smem = 4 * 64 * SP * (int)sizeof(float);   // 69,632 B
        cudaFuncSetAttribute(attn_kernel,
                             cudaFuncAttributeMaxDynamicSharedMemorySize, smem);
        dim3 grid(Tsz / 64, Bsz * Hn);
        attn_kernel<<<grid, 256, smem>>>();
    }

    // 3) out = y @ w_proj + b_proj  (M=8192, N=1024, K=1024)
    {
        dim3 grid(Csz / 128, Mrows / 128);
        gemm_proj_kernel<<<grid, 256>>>(w_proj, b_proj, out);
    }
}

// round 3
// speedup vs baseline: 1.7064x; 1.7064x over previous
#include <cuda_runtime.h>
#include <cuda_bf16.h>
#include <cstdint>
#include <cstddef>

#define Bsz   4
#define Tsz   2048
#define Csz   1024
#define Hn    16
#define Dh    64
#define Mrows (Bsz * Tsz)   // 8192

// Scratch (static __device__ arrays — allocation-guard safe)
__device__ float g_qkv [(size_t)Mrows * 3 * Csz];   // [8192, 3072]
__device__ float g_y   [(size_t)Mrows * Csz];       // [8192, 1024]  (tf32-rounded)
__device__ float g_xc  [(size_t)Mrows * Csz];       // x, tf32-rounded
__device__ float g_wqkvT[(size_t)3 * Csz * Csz];    // [3072, 1024]  (tf32-rounded)
__device__ float g_wpT [(size_t)Csz * Csz];         // [1024, 1024]  (tf32-rounded)

// ---------------------------------------------------------------------------
// Helpers (all non-'a' PTX: cp.async + mma.sync are sm_80 baseline features)
// ---------------------------------------------------------------------------
__device__ __forceinline__ uint32_t smem_to_u32(const void* p) {
    uint32_t a;
    asm("{ .reg .u64 t; cvta.to.shared.u64 t, %1; cvt.u32.u64 %0, t; }"
        : "=r"(a) : "l"(p));
    return a;
}
__device__ __forceinline__ float to_tf32(float x) {
    uint32_t r;
    asm("cvt.rna.tf32.f32 %0, %1;" : "=r"(r) : "f"(x));
    return __uint_as_float(r);
}

#define CP_ASYNC16(dst, src) \
    asm volatile("cp.async.cg.shared.global [%0], [%1], 16;" :: "r"(dst), "l"(src) : "memory")
#define CP_COMMIT() asm volatile("cp.async.commit_group;" ::: "memory")
#define CP_WAIT(n)  asm volatile("cp.async.wait_group %0;" :: "n"(n) : "memory")

// D += A*B, m16n8k8 tf32 (A row-major, B col-major i.e. [n][k])
#define MMA_TF32(d, a, b) \
    asm volatile("mma.sync.aligned.m16n8k8.row.col.f32.tf32.tf32.f32 " \
        "{%0,%1,%2,%3}, {%4,%5,%6,%7}, {%8,%9}, {%0,%1,%2,%3};" \
        : "+f"((d)[0]), "+f"((d)[1]), "+f"((d)[2]), "+f"((d)[3]) \
        : "r"((a)[0]), "r"((a)[1]), "r"((a)[2]), "r"((a)[3]), \
          "r"((b)[0]), "r"((b)[1]))

// ---------------------------------------------------------------------------
// mma.sync tf32 GEMM: C[M,N] = A[M,1024] @ Bt[N,1024]^T + bias
// CTA tile 128x128, BK=32, 3-stage cp.async, 256 threads (8 warps, 2x4),
// warp tile 64x32 via 4x4 m16n8k8 fragments. Swizzled smem, conflict-free.
// ---------------------------------------------------------------------------
#define KCHUNKS 32
#define STAGE_F 8192          // floats per stage (A 4096 + B 4096)
#define GEMM_SMEM (3 * STAGE_F * 4)

__global__ __launch_bounds__(256) void gemm_mma_kernel(
    const float* __restrict__ A,     // [M,1024] row-major (tf32-rounded)
    const float* __restrict__ Bt,    // [N,1024] row-major (tf32-rounded)
    const float* __restrict__ bias,  // [N] fp32
    float* __restrict__ C,           // [M,Ntot]
    int Ntot)
{
    extern __shared__ float sm[];
    uint32_t smemB = smem_to_u32(sm);

    int tid  = threadIdx.x;
    int lane = tid & 31;
    int warp = tid >> 5;
    int wm = warp >> 2;          // 0..1
    int wn = warp & 3;           // 0..3
    int tg = lane >> 2;          // 0..7
    int ti = lane & 3;           // 0..3
    int row0 = blockIdx.y * 128;
    int col0 = blockIdx.x * 128;

    // fragment row offsets (float index within a tile, stride 32 per row)
    int rowA0[4], rowA1[4], rowB[4];
    #pragma unroll
    for (int i = 0; i < 4; i++) {
        int m = wm * 64 + i * 16 + tg;
        rowA0[i] = m * 32;
        rowA1[i] = rowA0[i] + 8 * 32;
        rowB[i]  = (wn * 32 + i * 8 + tg) * 32;
    }
    int swz = tg * 4;

    float acc[4][4][4];
    #pragma unroll
    for (int i = 0; i < 4; i++)
        #pragma unroll
        for (int j = 0; j < 4; j++)
            #pragma unroll
            for (int q = 0; q < 4; q++) acc[i][j][q] = 0.f;

    auto load_stage = [&](int chunk) {
        if (chunk < KCHUNKS) {
            int s = chunk % 3;
            uint32_t base = smemB + (uint32_t)s * (STAGE_F * 4);
            #pragma unroll
            for (int j = 0; j < 4; j++) {
                int idx = tid + j * 256;
                int r   = idx >> 3;
                int c4  = (idx & 7) * 4;
                int sc  = c4 ^ ((r & 7) * 4);
                const float* ga = A  + (size_t)(row0 + r) * 1024 + chunk * 32 + c4;
                const float* gb = Bt + (size_t)(col0 + r) * 1024 + chunk * 32 + c4;
                CP_ASYNC16(base + (uint32_t)(r * 128 + sc * 4), ga);
                CP_ASYNC16(base + (uint32_t)(16384 + r * 128 + sc * 4), gb);
            }
        }
        CP_COMMIT();
    };

    load_stage(0);
    load_stage(1);
    load_stage(2);

    #pragma unroll 1
    for (int c = 0; c < KCHUNKS; ++c) {
        CP_WAIT(2);
        __syncthreads();

        const float* As = sm + (c % 3) * STAGE_F;
        const float* Bs = As + 4096;

        #pragma unroll
        for (int ks = 0; ks < 4; ks++) {
            int k0 = ks * 8 + ti;
            int c0 = k0 ^ swz;
            int c1 = (k0 + 4) ^ swz;

            uint32_t af[4][4], bf[4][2];
            #pragma unroll
            for (int i = 0; i < 4; i++) {
                af[i][0] = __float_as_uint(As[rowA0[i] + c0]);
                af[i][1] = __float_as_uint(As[rowA1[i] + c0]);
                af[i][2] = __float_as_uint(As[rowA0[i] + c1]);
                af[i][3] = __float_as_uint(As[rowA1[i] + c1]);
            }
            #pragma unroll
            for (int j = 0; j < 4; j++) {
                bf[j][0] = __float_as_uint(Bs[rowB[j] + c0]);
                bf[j][1] = __float_as_uint(Bs[rowB[j] + c1]);
            }
            #pragma unroll
            for (int i = 0; i < 4; i++)
                #pragma unroll
                for (int j = 0; j < 4; j++)
                    MMA_TF32(acc[i][j], af[i], bf[j]);
        }

        __syncthreads();
        load_stage(c + 3);
    }

    // epilogue: fragment layout c0:(m, n) c1:(m, n+1) c2:(m+8, n) c3:(m+8, n+1)
    #pragma unroll
    for (int i = 0; i < 4; i++) {
        int m = row0 + wm * 64 + i * 16 + tg;
        #pragma unroll
        for (int j = 0; j < 4; j++) {
            int n = col0 + wn * 32 + j * 8 + 2 * ti;
            float bx = __ldg(bias + n);
            float by = __ldg(bias + n + 1);
            float2 o0 = make_float2(acc[i][j][0] + bx, acc[i][j][1] + by);
            float2 o1 = make_float2(acc[i][j][2] + bx, acc[i][j][3] + by);
            *(float2*)&C[(size_t)m * Ntot + n] = o0;
            *(float2*)&C[(size_t)(m + 8) * Ntot + n] = o1;
        }
    }
}

// ---------------------------------------------------------------------------
// x -> tf32-rounded copy (vectorized)
// ---------------------------------------------------------------------------
__global__ __launch_bounds__(256) void cvt4_kernel(
    const float4* __restrict__ in, float4* __restrict__ out, int n4)
{
    int i = blockIdx.x * 256 + threadIdx.x;
    if (i < n4) {
        float4 v = in[i];
        v.x = to_tf32(v.x); v.y = to_tf32(v.y);
        v.z = to_tf32(v.z); v.w = to_tf32(v.w);
        out[i] = v;
    }
}

// ---------------------------------------------------------------------------
// 32x32 tiled transpose + tf32 round: out[c][r] = tf32(in[r][c])
// ---------------------------------------------------------------------------
__global__ __launch_bounds__(256) void transpose_cvt_kernel(
    const float* __restrict__ in, float* __restrict__ out, int R, int C)
{
    __shared__ float t[32][33];
    int c0 = blockIdx.x * 32, r0 = blockIdx.y * 32;
    int tx = threadIdx.x & 31, ty = threadIdx.x >> 5;
    #pragma unroll
    for (int i = ty; i < 32; i += 8)
        t[i][tx] = in[(size_t)(r0 + i) * C + c0 + tx];
    __syncthreads();
    #pragma unroll
    for (int i = ty; i < 32; i += 8)
        out[(size_t)(c0 + i) * R + r0 + tx] = to_tf32(t[tx][i]);
}

// ---------------------------------------------------------------------------
// Flash attention, fp32 SIMT (round-0 proven). Output tf32-rounded for proj.
// ---------------------------------------------------------------------------
#define SP 68

__global__ __launch_bounds__(256) void attn_kernel()
{
    extern __shared__ float smf[];
    float* Qt = smf;
    float* Kt = Qt + 64 * SP;
    float* Vs = Kt + 64 * SP;
    float* Pt = Vs + 64 * SP;

    int qb = blockIdx.x;
    int bh = blockIdx.y;
    int b = bh >> 4, h = bh & 15;
    int tid = threadIdx.x;
    int tx = tid & 15, ty = tid >> 4;

    for (int i = tid; i < 64 * 64; i += 256) {
        int r = i >> 6, d = i & 63;
        Qt[d * SP + r] =
            g_qkv[(size_t)(b * Tsz + qb * 64 + r) * (3 * Csz) + h * Dh + d];
    }

    float m[4], l[4], acc[4][4];
    #pragma unroll
    for (int i = 0; i < 4; i++) {
        m[i] = -1e30f; l[i] = 0.f;
        #pragma unroll
        for (int j = 0; j < 4; j++) acc[i][j] = 0.f;
    }

    for (int kb = 0; kb <= qb; kb++) {
        __syncthreads();
        for (int i = tid; i < 64 * 64; i += 256) {
            int r = i >> 6, d = i & 63;
            size_t g = (size_t)(b * Tsz + kb * 64 + r) * (3 * Csz) + h * Dh + d;
            Kt[d * SP + r] = g_qkv[g + Csz];
            Vs[r * SP + d] = g_qkv[g + 2 * Csz];
        }
        __syncthreads();

        float s[4][4];
        #pragma unroll
        for (int i = 0; i < 4; i++)
            #pragma unroll
            for (int j = 0; j < 4; j++) s[i][j] = 0.f;

        #pragma unroll 8
        for (int d = 0; d < 64; d++) {
            float4 q4 = *(float4*)&Qt[d * SP + ty * 4];
            float4 k4 = *(float4*)&Kt[d * SP + tx * 4];
            float qa[4] = {q4.x, q4.y, q4.z, q4.w};
            float ka[4] = {k4.x, k4.y, k4.z, k4.w};
            #pragma unroll
            for (int i = 0; i < 4; i++)
                #pragma unroll
                for (int j = 0; j < 4; j++)
                    s[i][j] += qa[i] * ka[j];
        }

        bool diag = (kb == qb);
        #pragma unroll
        for (int i = 0; i < 4; i++)
            #pragma unroll
            for (int j = 0; j < 4; j++) {
                s[i][j] *= 0.125f;
                if (diag && (tx * 4 + j) > (ty * 4 + i)) s[i][j] = -1e30f;
            }

        #pragma unroll
        for (int i = 0; i < 4; i++) {
            float mt = fmaxf(fmaxf(s[i][0], s[i][1]), fmaxf(s[i][2], s[i][3]));
            mt = fmaxf(mt, __shfl_xor_sync(0xffffffffu, mt, 1));
            mt = fmaxf(mt, __shfl_xor_sync(0xffffffffu, mt, 2));
            mt = fmaxf(mt, __shfl_xor_sync(0xffffffffu, mt, 4));
            mt = fmaxf(mt, __shfl_xor_sync(0xffffffffu, mt, 8));
            float mn = fmaxf(m[i], mt);
            float sc = __expf(m[i] - mn);
            float ps = 0.f;
            #pragma unroll
            for (int j = 0; j < 4; j++) {
                float p = __expf(s[i][j] - mn);
                s[i][j] = p;
                ps += p;
            }
            ps += __shfl_xor_sync(0xffffffffu, ps, 1);
            ps += __shfl_xor_sync(0xffffffffu, ps, 2);
            ps += __shfl_xor_sync(0xffffffffu, ps, 4);
            ps += __shfl_xor_sync(0xffffffffu, ps, 8);
            l[i] = l[i] * sc + ps;
            m[i] = mn;
            #pragma unroll
            for (int j = 0; j < 4; j++) {
                acc[i][j] *= sc;
                Pt[(tx * 4 + j) * SP + ty * 4 + i] = s[i][j];
            }
        }
        __syncthreads();

        #pragma unroll 8
        for (int j = 0; j < 64; j++) {
            float4 p4 = *(float4*)&Pt[j * SP + ty * 4];
            float4 v4 = *(float4*)&Vs[j * SP + tx * 4];
            float pa[4] = {p4.x, p4.y, p4.z, p4.w};
            float va[4] = {v4.x, v4.y, v4.z, v4.w};
            #pragma unroll
            for (int i = 0; i < 4; i++)
                #pragma unroll
                for (int jd = 0; jd < 4; jd++)
                    acc[i][jd] += pa[i] * va[jd];
        }
    }

    #pragma unroll
    for (int i = 0; i < 4; i++) {
        float inv = 1.f / l[i];
        float4 o;
        o.x = to_tf32(acc[i][0] * inv);
        o.y = to_tf32(acc[i][1] * inv);
        o.z = to_tf32(acc[i][2] * inv);
        o.w = to_tf32(acc[i][3] * inv);
        *(float4*)&g_y[(size_t)(b * Tsz + qb * 64 + ty * 4 + i) * Csz
                       + h * Dh + tx * 4] = o;
    }
}

// ---------------------------------------------------------------------------
extern "C" void kernel_launch(void* const* d_in, const int* in_sizes, int n_in,
                              void* d_out, int out_size)
{
    const float* x      = (const float*)d_in[0];
    const float* w_qkv  = (const float*)d_in[1];
    const float* b_qkv  = (const float*)d_in[2];
    const float* w_proj = (const float*)d_in[3];
    const float* b_proj = (const float*)d_in[4];
    float* out = (float*)d_out;

    float* wqkvT; cudaGetSymbolAddress((void**)&wqkvT, g_wqkvT);
    float* wpT;   cudaGetSymbolAddress((void**)&wpT,   g_wpT);
    float* qkv;   cudaGetSymbolAddress((void**)&qkv,   g_qkv);
    float* y;     cudaGetSymbolAddress((void**)&y,     g_y);
    float* xc;    cudaGetSymbolAddress((void**)&xc,    g_xc);

    // 0) prep: tf32-round x; transpose+round weights
    {
        int n4 = Mrows * Csz / 4;
        cvt4_kernel<<<n4 / 256, 256>>>((const float4*)x, (float4*)xc, n4);
        dim3 g1(3 * Csz / 32, Csz / 32);
        transpose_cvt_kernel<<<g1, 256>>>(w_qkv, wqkvT, Csz, 3 * Csz);
        dim3 g2(Csz / 32, Csz / 32);
        transpose_cvt_kernel<<<g2, 256>>>(w_proj, wpT, Csz, Csz);
    }

    // 1) qkv = x @ w_qkv + b_qkv  (mma.sync tf32)
    {
        cudaFuncSetAttribute(gemm_mma_kernel,
                             cudaFuncAttributeMaxDynamicSharedMemorySize, GEMM_SMEM);
        dim3 grid(3 * Csz / 128, Mrows / 128);
        gemm_mma_kernel<<<grid, 256, GEMM_SMEM>>>(xc, wqkvT, b_qkv, qkv, 3 * Csz);
    }

    // 2) flash attention -> g_y (tf32-rounded)
    {
        int smem = 4 * 64 * SP * (int)sizeof(float);
        cudaFuncSetAttribute(attn_kernel,
                             cudaFuncAttributeMaxDynamicSharedMemorySize, smem);
        dim3 grid(Tsz / 64, Bsz * Hn);
        attn_kernel<<<grid, 256, smem>>>();
    }

    // 3) out = y @ w_proj + b_proj  (mma.sync tf32)
    {
        dim3 grid(Csz / 128, Mrows / 128);
        gemm_mma_kernel<<<grid, 256, GEMM_SMEM>>>(y, wpT, b_proj, out, Csz);
    }
}

// round 5
// speedup vs baseline: 3.7084x; 2.1732x over previous
#include <cuda_runtime.h>
#include <cuda_bf16.h>
#include <cstdint>
#include <cstddef>

#define Bsz   4
#define Tsz   2048
#define Csz   1024
#define Hn    16
#define Dh    64
#define Mrows (Bsz * Tsz)   // 8192

// Scratch (static __device__ arrays — allocation-guard safe)
__device__ float g_qkv [(size_t)Mrows * 3 * Csz];   // [8192, 3072] (q,k thirds used)
__device__ float g_vT  [(size_t)Bsz * Hn * Dh * Tsz]; // [64 bh][64 d][2048 t]
__device__ float g_y   [(size_t)Mrows * Csz];       // [8192, 1024]  (tf32-rounded)
__device__ float g_xc  [(size_t)Mrows * Csz];       // x, tf32-rounded
__device__ float g_wqkvT[(size_t)3 * Csz * Csz];    // [3072, 1024]  (tf32-rounded)
__device__ float g_wpT [(size_t)Csz * Csz];         // [1024, 1024]  (tf32-rounded)

// ---------------------------------------------------------------------------
// Helpers (non-'a' PTX only: cp.async + mma.sync, sm_80 baseline)
// ---------------------------------------------------------------------------
__device__ __forceinline__ uint32_t smem_to_u32(const void* p) {
    uint32_t a;
    asm("{ .reg .u64 t; cvta.to.shared.u64 t, %1; cvt.u32.u64 %0, t; }"
        : "=r"(a) : "l"(p));
    return a;
}
__device__ __forceinline__ float to_tf32(float x) {
    uint32_t r;
    asm("cvt.rna.tf32.f32 %0, %1;" : "=r"(r) : "f"(x));
    return __uint_as_float(r);
}

#define CP_ASYNC16(dst, src) \
    asm volatile("cp.async.cg.shared.global [%0], [%1], 16;" :: "r"(dst), "l"(src) : "memory")
#define CP_COMMIT() asm volatile("cp.async.commit_group;" ::: "memory")
#define CP_WAIT(n)  asm volatile("cp.async.wait_group %0;" :: "n"(n) : "memory")

// D += A*B, m16n8k8 tf32 (A row-major, B col-major i.e. [n][k])
#define MMA_TF32(d, a, b) \
    asm volatile("mma.sync.aligned.m16n8k8.row.col.f32.tf32.tf32.f32 " \
        "{%0,%1,%2,%3}, {%4,%5,%6,%7}, {%8,%9}, {%0,%1,%2,%3};" \
        : "+f"((d)[0]), "+f"((d)[1]), "+f"((d)[2]), "+f"((d)[3]) \
        : "r"((a)[0]), "r"((a)[1]), "r"((a)[2]), "r"((a)[3]), \
          "r"((b)[0]), "r"((b)[1]))

// ---------------------------------------------------------------------------
// mma.sync tf32 GEMM: C[M,N] = A[M,1024] @ Bt[N,1024]^T + bias
// 128x128 tile, BK=32, 3-stage cp.async, 256 threads, warp tile 64x32.
// If vT != nullptr, tiles with col0 >= 2048 (the V third of qkv) are scattered
// to vT[bh][d][t] instead. roundC: tf32-round outputs.
// ---------------------------------------------------------------------------
#define KCHUNKS 32
#define STAGE_F 8192
#define GEMM_SMEM (3 * STAGE_F * 4)

__global__ __launch_bounds__(256) void gemm_mma_kernel(
    const float* __restrict__ A,
    const float* __restrict__ Bt,
    const float* __restrict__ bias,
    float* __restrict__ C,
    int Ntot,
    float* __restrict__ vT,
    int roundC)
{
    extern __shared__ float sm[];
    uint32_t smemB = smem_to_u32(sm);

    int tid  = threadIdx.x;
    int lane = tid & 31;
    int warp = tid >> 5;
    int wm = warp >> 2;
    int wn = warp & 3;
    int tg = lane >> 2;
    int ti = lane & 3;
    int row0 = blockIdx.y * 128;
    int col0 = blockIdx.x * 128;

    int rowA0[4], rowA1[4], rowB[4];
    #pragma unroll
    for (int i = 0; i < 4; i++) {
        int m = wm * 64 + i * 16 + tg;
        rowA0[i] = m * 32;
        rowA1[i] = rowA0[i] + 8 * 32;
        rowB[i]  = (wn * 32 + i * 8 + tg) * 32;
    }
    int swz = tg * 4;

    float acc[4][4][4];
    #pragma unroll
    for (int i = 0; i < 4; i++)
        #pragma unroll
        for (int j = 0; j < 4; j++)
            #pragma unroll
            for (int q = 0; q < 4; q++) acc[i][j][q] = 0.f;

    auto load_stage = [&](int chunk) {
        if (chunk < KCHUNKS) {
            int s = chunk % 3;
            uint32_t base = smemB + (uint32_t)s * (STAGE_F * 4);
            #pragma unroll
            for (int j = 0; j < 4; j++) {
                int idx = tid + j * 256;
                int r   = idx >> 3;
                int c4  = (idx & 7) * 4;
                int sc  = c4 ^ ((r & 7) * 4);
                const float* ga = A  + (size_t)(row0 + r) * 1024 + chunk * 32 + c4;
                const float* gb = Bt + (size_t)(col0 + r) * 1024 + chunk * 32 + c4;
                CP_ASYNC16(base + (uint32_t)(r * 128 + sc * 4), ga);
                CP_ASYNC16(base + (uint32_t)(16384 + r * 128 + sc * 4), gb);
            }
        }
        CP_COMMIT();
    };

    load_stage(0);
    load_stage(1);
    load_stage(2);

    #pragma unroll 1
    for (int c = 0; c < KCHUNKS; ++c) {
        CP_WAIT(2);
        __syncthreads();

        const float* As = sm + (c % 3) * STAGE_F;
        const float* Bs = As + 4096;

        #pragma unroll
        for (int ks = 0; ks < 4; ks++) {
            int k0 = ks * 8 + ti;
            int c0 = k0 ^ swz;
            int c1 = (k0 + 4) ^ swz;

            uint32_t af[4][4], bf[4][2];
            #pragma unroll
            for (int i = 0; i < 4; i++) {
                af[i][0] = __float_as_uint(As[rowA0[i] + c0]);
                af[i][1] = __float_as_uint(As[rowA1[i] + c0]);
                af[i][2] = __float_as_uint(As[rowA0[i] + c1]);
                af[i][3] = __float_as_uint(As[rowA1[i] + c1]);
            }
            #pragma unroll
            for (int j = 0; j < 4; j++) {
                bf[j][0] = __float_as_uint(Bs[rowB[j] + c0]);
                bf[j][1] = __float_as_uint(Bs[rowB[j] + c1]);
            }
            #pragma unroll
            for (int i = 0; i < 4; i++)
                #pragma unroll
                for (int j = 0; j < 4; j++)
                    MMA_TF32(acc[i][j], af[i], bf[j]);
        }

        __syncthreads();
        load_stage(c + 3);
    }

    bool vtile = (vT != nullptr) && (col0 >= 2048);

    #pragma unroll
    for (int i = 0; i < 4; i++) {
        int m = row0 + wm * 64 + i * 16 + tg;
        #pragma unroll
        for (int j = 0; j < 4; j++) {
            int n = col0 + wn * 32 + j * 8 + 2 * ti;
            float bx = __ldg(bias + n);
            float by = __ldg(bias + n + 1);
            float v0 = acc[i][j][0] + bx;
            float v1 = acc[i][j][1] + by;
            float v2 = acc[i][j][2] + bx;
            float v3 = acc[i][j][3] + by;
            if (roundC) {
                v0 = to_tf32(v0); v1 = to_tf32(v1);
                v2 = to_tf32(v2); v3 = to_tf32(v3);
            }
            if (vtile) {
                int d0 = n - 2048;
                int t  = m & 2047;
                int bb = m >> 11;
                float* p0 = vT + ((size_t)((bb << 4) | (d0 >> 6)) * 64 + (d0 & 63)) * 2048 + t;
                float* p1 = vT + ((size_t)((bb << 4) | ((d0 + 1) >> 6)) * 64 + ((d0 + 1) & 63)) * 2048 + t;
                p0[0] = v0; p0[8] = v2;
                p1[0] = v1; p1[8] = v3;
            } else {
                *(float2*)&C[(size_t)m * Ntot + n] = make_float2(v0, v1);
                *(float2*)&C[(size_t)(m + 8) * Ntot + n] = make_float2(v2, v3);
            }
        }
    }
}

// ---------------------------------------------------------------------------
// prep kernels
// ---------------------------------------------------------------------------
__global__ __launch_bounds__(256) void cvt4_kernel(
    const float4* __restrict__ in, float4* __restrict__ out, int n4)
{
    int i = blockIdx.x * 256 + threadIdx.x;
    if (i < n4) {
        float4 v = in[i];
        v.x = to_tf32(v.x); v.y = to_tf32(v.y);
        v.z = to_tf32(v.z); v.w = to_tf32(v.w);
        out[i] = v;
    }
}

__global__ __launch_bounds__(256) void transpose_cvt_kernel(
    const float* __restrict__ in, float* __restrict__ out, int R, int C)
{
    __shared__ float t[32][33];
    int c0 = blockIdx.x * 32, r0 = blockIdx.y * 32;
    int tx = threadIdx.x & 31, ty = threadIdx.x >> 5;
    #pragma unroll
    for (int i = ty; i < 32; i += 8)
        t[i][tx] = in[(size_t)(r0 + i) * C + c0 + tx];
    __syncthreads();
    #pragma unroll
    for (int i = ty; i < 32; i += 8)
        out[(size_t)(c0 + i) * R + r0 + tx] = to_tf32(t[tx][i]);
}

// ---------------------------------------------------------------------------
// Tensor-core flash attention (tf32 mma.sync).
// Grid (16, 64): x = q-block (reversed for heavy-first), y = b*16+h.
// 256 threads, 8 warps, each warp owns 16 query rows.
// Smem: Qs[128][68] + 2 stages of { Ks[64][68], Vt[64][68] }.
// ---------------------------------------------------------------------------
#define AS 68
#define ATT_SMEM (384 * AS * 4)   // (128 + 4*64) rows * 68 floats

__global__ __launch_bounds__(256, 2) void attn_mma_kernel()
{
    extern __shared__ float sm[];
    uint32_t smemB = smem_to_u32(sm);

    int qb = gridDim.x - 1 - blockIdx.x;       // heavy blocks first
    int bh = blockIdx.y;
    int b = bh >> 4, h = bh & 15;
    int tid = threadIdx.x, lane = tid & 31, warp = tid >> 5;
    int tg = lane >> 2, ti = lane & 3;
    int q0 = qb * 128;
    int kmax = 2 * qb + 1;

    // Q tile -> Qs (natural [query][d], stride AS): 128x64 floats = 2048 chunks
    {
        #pragma unroll
        for (int u = 0; u < 8; u++) {
            int i = tid + u * 256;
            int r = i >> 4, c4 = (i & 15) * 4;
            const float* src = g_qkv + (size_t)(b * Tsz + q0 + r) * 3072 + h * 64 + c4;
            CP_ASYNC16(smemB + (uint32_t)(r * AS + c4) * 4, src);
        }
        CP_COMMIT();
    }

    auto load_kv = [&](int kb) {
        if (kb <= kmax) {
            uint32_t kB = smemB + (uint32_t)(128 * AS + (kb & 1) * 2 * 64 * AS) * 4;
            // K tile: 64x64 floats = 1024 chunks (4 per thread)
            #pragma unroll
            for (int u = 0; u < 4; u++) {
                int i = tid + u * 256;
                int r = i >> 4, c4 = (i & 15) * 4;
                const float* kg = g_qkv + (size_t)(b * Tsz + kb * 64 + r) * 3072 + 1024 + h * 64 + c4;
                CP_ASYNC16(kB + (uint32_t)(r * AS + c4) * 4, kg);
                const float* vg = g_vT + ((size_t)bh * 64 + r) * Tsz + kb * 64 + c4;   // r = d
                CP_ASYNC16(kB + (uint32_t)(64 * AS + r * AS + c4) * 4, vg);
            }
        }
        CP_COMMIT();
    };

    load_kv(0);
    load_kv(1);

    float o[8][4];
    #pragma unroll
    for (int j = 0; j < 8; j++)
        #pragma unroll
        for (int q = 0; q < 4; q++) o[j][q] = 0.f;
    float mr[2] = {-1e30f, -1e30f}, lr[2] = {0.f, 0.f};

    const float* Qs = sm;
    int ra0 = (warp * 16 + tg) * AS;
    int ra1 = ra0 + 8 * AS;

    #pragma unroll 1
    for (int kb = 0; kb <= kmax; kb++) {
        CP_WAIT(1);
        __syncthreads();
        const float* Ks = sm + 128 * AS + (kb & 1) * (2 * 64 * AS);
        const float* Vt = Ks + 64 * AS;

        // ---- S = Q K^T ----
        float s[8][4];
        #pragma unroll
        for (int j = 0; j < 8; j++)
            #pragma unroll
            for (int q = 0; q < 4; q++) s[j][q] = 0.f;

        #pragma unroll
        for (int kt = 0; kt < 8; kt++) {
            int k0 = kt * 8 + ti;
            uint32_t af[4];
            af[0] = __float_as_uint(Qs[ra0 + k0]);
            af[1] = __float_as_uint(Qs[ra1 + k0]);
            af[2] = __float_as_uint(Qs[ra0 + k0 + 4]);
            af[3] = __float_as_uint(Qs[ra1 + k0 + 4]);
            #pragma unroll
            for (int j = 0; j < 8; j++) {
                uint32_t bf[2];
                bf[0] = __float_as_uint(Ks[(j * 8 + tg) * AS + k0]);
                bf[1] = __float_as_uint(Ks[(j * 8 + tg) * AS + k0 + 4]);
                MMA_TF32(s[j], af, bf);
            }
        }

        // ---- scale + causal mask ----
        if (kb >= 2 * qb) {
            int row0 = q0 + warp * 16 + tg;
            #pragma unroll
            for (int j = 0; j < 8; j++) {
                int col = kb * 64 + j * 8 + 2 * ti;
                s[j][0] = (col     > row0    ) ? -1e30f : s[j][0] * 0.125f;
                s[j][1] = (col + 1 > row0    ) ? -1e30f : s[j][1] * 0.125f;
                s[j][2] = (col     > row0 + 8) ? -1e30f : s[j][2] * 0.125f;
                s[j][3] = (col + 1 > row0 + 8) ? -1e30f : s[j][3] * 0.125f;
            }
        } else {
            #pragma unroll
            for (int j = 0; j < 8; j++)
                #pragma unroll
                for (int q = 0; q < 4; q++) s[j][q] *= 0.125f;
        }

        // ---- online softmax (rows tg, tg+8; spread over quad) ----
        float mt0 = -1e30f, mt1 = -1e30f;
        #pragma unroll
        for (int j = 0; j < 8; j++) {
            mt0 = fmaxf(mt0, fmaxf(s[j][0], s[j][1]));
            mt1 = fmaxf(mt1, fmaxf(s[j][2], s[j][3]));
        }
        mt0 = fmaxf(mt0, __shfl_xor_sync(0xffffffffu, mt0, 1));
        mt0 = fmaxf(mt0, __shfl_xor_sync(0xffffffffu, mt0, 2));
        mt1 = fmaxf(mt1, __shfl_xor_sync(0xffffffffu, mt1, 1));
        mt1 = fmaxf(mt1, __shfl_xor_sync(0xffffffffu, mt1, 2));

        float mn0 = fmaxf(mr[0], mt0), mn1 = fmaxf(mr[1], mt1);
        float sc0 = __expf(mr[0] - mn0), sc1 = __expf(mr[1] - mn1);
        float ps0 = 0.f, ps1 = 0.f;
        #pragma unroll
        for (int j = 0; j < 8; j++) {
            s[j][0] = __expf(s[j][0] - mn0); ps0 += s[j][0];
            s[j][1] = __expf(s[j][1] - mn0); ps0 += s[j][1];
            s[j][2] = __expf(s[j][2] - mn1); ps1 += s[j][2];
            s[j][3] = __expf(s[j][3] - mn1); ps1 += s[j][3];
        }
        ps0 += __shfl_xor_sync(0xffffffffu, ps0, 1);
        ps0 += __shfl_xor_sync(0xffffffffu, ps0, 2);
        ps1 += __shfl_xor_sync(0xffffffffu, ps1, 1);
        ps1 += __shfl_xor_sync(0xffffffffu, ps1, 2);
        lr[0] = lr[0] * sc0 + ps0; mr[0] = mn0;
        lr[1] = lr[1] * sc1 + ps1; mr[1] = mn1;

        #pragma unroll
        for (int j = 0; j < 8; j++) {
            o[j][0] *= sc0; o[j][1] *= sc0;
            o[j][2] *= sc1; o[j][3] *= sc1;
            s[j][0] = to_tf32(s[j][0]); s[j][1] = to_tf32(s[j][1]);
            s[j][2] = to_tf32(s[j][2]); s[j][3] = to_tf32(s[j][3]);
        }

        // ---- O += P V  (A-frags built from S-acc via quad shfl) ----
        int src0 = (lane & ~3) | (ti >> 1);
        int src1 = src0 + 2;
        bool odd = (ti & 1) != 0;
        #pragma unroll
        for (int kt = 0; kt < 8; kt++) {
            float v00 = __shfl_sync(0xffffffffu, s[kt][0], src0);
            float v01 = __shfl_sync(0xffffffffu, s[kt][1], src0);
            float v02 = __shfl_sync(0xffffffffu, s[kt][2], src0);
            float v03 = __shfl_sync(0xffffffffu, s[kt][3], src0);
            float v10 = __shfl_sync(0xffffffffu, s[kt][0], src1);
            float v11 = __shfl_sync(0xffffffffu, s[kt][1], src1);
            float v12 = __shfl_sync(0xffffffffu, s[kt][2], src1);
            float v13 = __shfl_sync(0xffffffffu, s[kt][3], src1);
            uint32_t af[4];
            af[0] = __float_as_uint(odd ? v01 : v00);
            af[1] = __float_as_uint(odd ? v03 : v02);
            af[2] = __float_as_uint(odd ? v11 : v10);
            af[3] = __float_as_uint(odd ? v13 : v12);
            int k0 = kt * 8 + ti;
            #pragma unroll
            for (int jd = 0; jd < 8; jd++) {
                uint32_t bf[2];
                bf[0] = __float_as_uint(Vt[(jd * 8 + tg) * AS + k0]);
                bf[1] = __float_as_uint(Vt[(jd * 8 + tg) * AS + k0 + 4]);
                MMA_TF32(o[jd], af, bf);
            }
        }

        __syncthreads();
        load_kv(kb + 2);
    }

    // ---- epilogue: normalize + tf32-round + store y[B,T,C] ----
    float i0 = 1.f / lr[0], i1 = 1.f / lr[1];
    size_t m0 = (size_t)(b * Tsz + q0 + warp * 16 + tg);
    #pragma unroll
    for (int jd = 0; jd < 8; jd++) {
        int col = h * 64 + jd * 8 + 2 * ti;
        float2 w0 = make_float2(to_tf32(o[jd][0] * i0), to_tf32(o[jd][1] * i0));
        float2 w1 = make_float2(to_tf32(o[jd][2] * i1), to_tf32(o[jd][3] * i1));
        *(float2*)&g_y[m0 * 1024 + col] = w0;
        *(float2*)&g_y[(m0 + 8) * 1024 + col] = w1;
    }
}

// ---------------------------------------------------------------------------
extern "C" void kernel_launch(void* const* d_in, const int* in_sizes, int n_in,
                              void* d_out, int out_size)
{
    const float* x      = (const float*)d_in[0];
    const float* w_qkv  = (const float*)d_in[1];
    const float* b_qkv  = (const float*)d_in[2];
    const float* w_proj = (const float*)d_in[3];
    const float* b_proj = (const float*)d_in[4];
    float* out = (float*)d_out;

    float* wqkvT; cudaGetSymbolAddress((void**)&wqkvT, g_wqkvT);
    float* wpT;   cudaGetSymbolAddress((void**)&wpT,   g_wpT);
    float* qkv;   cudaGetSymbolAddress((void**)&qkv,   g_qkv);
    float* y;     cudaGetSymbolAddress((void**)&y,     g_y);
    float* xc;    cudaGetSymbolAddress((void**)&xc,    g_xc);
    float* vT;    cudaGetSymbolAddress((void**)&vT,    g_vT);

    // 0) prep: tf32-round x; transpose+round weights
    {
        int n4 = Mrows * Csz / 4;
        cvt4_kernel<<<n4 / 256, 256>>>((const float4*)x, (float4*)xc, n4);
        dim3 g1(3 * Csz / 32, Csz / 32);
        transpose_cvt_kernel<<<g1, 256>>>(w_qkv, wqkvT, Csz, 3 * Csz);
        dim3 g2(Csz / 32, Csz / 32);
        transpose_cvt_kernel<<<g2, 256>>>(w_proj, wpT, Csz, Csz);
    }

    // 1) qkv = x @ w_qkv + b_qkv  (q,k -> g_qkv; v -> g_vT transposed; rounded)
    {
        cudaFuncSetAttribute(gemm_mma_kernel,
                             cudaFuncAttributeMaxDynamicSharedMemorySize, GEMM_SMEM);
        dim3 grid(3 * Csz / 128, Mrows / 128);
        gemm_mma_kernel<<<grid, 256, GEMM_SMEM>>>(xc, wqkvT, b_qkv, qkv, 3 * Csz, vT, 1);
    }

    // 2) tensor-core flash attention -> g_y
    {
        cudaFuncSetAttribute(attn_mma_kernel,
                             cudaFuncAttributeMaxDynamicSharedMemorySize, ATT_SMEM);
        dim3 grid(Tsz / 128, Bsz * Hn);
        attn_mma_kernel<<<grid, 256, ATT_SMEM>>>();
    }

    // 3) out = y @ w_proj + b_proj
    {
        dim3 grid(Csz / 128, Mrows / 128);
        gemm_mma_kernel<<<grid, 256, GEMM_SMEM>>>(y, wpT, b_proj, out, Csz, nullptr, 0);
    }
}